// round 8
// baseline (speedup 1.0000x reference)
#include <cuda_runtime.h>

// FullNet_29008209117719: tau[N,48,9] = a[n,j] * T[ch,j]
//   T[ch,j] = exp(w_lin[j,ch]) * (j<2 ? 1 : FILT[j-2,ch])   (constant per launch)
//   a[n,0]=c[n,0]; a[n,1]=c[n,1]; a[n,2+g]=c[n,2+g]*sigmoid(MLP_g(t_p[n]))
// Store-bound: 453 MB output. R5 structure (best measured) with smem cut to
// ~37.7KB (weights read directly from gmem, broadcast LDG) so 6 CTAs/SM fit:
// 888 concurrent CTAs -> 1.15-wave tail (was 1.38) and 48 warps/SM of store
// overlap. Store loop unchanged: 2x LDS.128 + 4 FMUL + 1 streaming STG.128,
// all stores 128B-aligned full lines.

#define NTH 256
#define NS  256            // samples per block (1 per thread)
#define ROW 432            // 48 channels * 9 species
#define NF4 (ROW / 4)      // 108 float4 per sample row
#define WCHUNK 3456        // f4s per warp = 32 samples * 108

__device__ __constant__ unsigned char d_F16[7][16] = {
    {1,1,1,1,1,1,1,1,1,1,1,1,1,0,1,1},  // h2o
    {0,0,0,1,1,0,1,1,0,0,0,0,1,0,0,0},  // o3
    {0,0,1,1,1,1,1,1,0,0,0,1,1,1,1,0},  // co2
    {1,0,0,0,0,0,0,0,0,0,1,0,0,0,0,0},  // o2
    {0,0,1,0,0,0,0,1,1,0,0,0,1,0,1,0},  // n2o
    {0,0,0,0,0,0,0,0,1,0,0,0,0,0,0,1},  // ch4
    {0,0,0,0,0,0,0,1,0,0,0,0,1,0,0,0},  // co
};

__global__ __launch_bounds__(NTH, 6) void fullnet_kernel(
    const float* __restrict__ t_p,   // [N,2]
    const float* __restrict__ c,     // [N,9]
    const float* __restrict__ w_lin, // [9,48]
    const float* __restrict__ W1, const float* __restrict__ b1,
    const float* __restrict__ W2, const float* __restrict__ b2,
    const float* __restrict__ W3, const float* __restrict__ b3,
    const float* __restrict__ Wo, const float* __restrict__ bo,
    float* __restrict__ out,         // [N,48,9]
    int Ntot)
{
    __shared__ float4 sT4[NF4];       // T table as 108 float4 (1728 B)
    __shared__ float4 sa4[NS][9];     // per-sample pre-gathered scalars (36 KB)

    const int tid  = threadIdx.x;
    const int lane = tid & 31;
    const int warp = tid >> 5;

    // ---- build constant table T ----
    float* sTf = (float*)sT4;
    for (int k = tid; k < ROW; k += NTH) {
        int ch = k / 9, j = k % 9;
        float m = (j < 2) ? 1.0f : (float)d_F16[j - 2][ch / 3];
        sTf[k] = m * expf(__ldg(&w_lin[j * 48 + ch]));
    }

    // ---- per-sample loads ----
    const int n = blockIdx.x * NS + tid;
    float tt = 0.f, pp = 0.f;
    float a[9];
    if (n < Ntot) {
        tt = t_p[2 * n];
        pp = t_p[2 * n + 1];
        #pragma unroll
        for (int j = 0; j < 9; j++) a[j] = c[9 * n + j];
    } else {
        #pragma unroll
        for (int j = 0; j < 9; j++) a[j] = 0.f;
    }

    // ---- MLPs (one sample per thread); weights via broadcast LDG ----
    #pragma unroll 1
    for (int g = 0; g < 7; g++) {
        const float* w1 = W1 + g * 12;
        const float* B1 = b1 + g * 6;
        float h1[6];
        #pragma unroll
        for (int h = 0; h < 6; h++) {
            float v = fmaf(__ldg(&w1[2 * h]), tt,
                      fmaf(__ldg(&w1[2 * h + 1]), pp, __ldg(&B1[h])));
            h1[h] = v > 0.f ? v : 0.f;
        }
        const float* w2 = W2 + g * 24;
        const float* B2 = b2 + g * 4;
        float h2[4];
        #pragma unroll
        for (int o = 0; o < 4; o++) {
            float v = __ldg(&B2[o]);
            #pragma unroll
            for (int h = 0; h < 6; h++) v = fmaf(__ldg(&w2[o * 6 + h]), h1[h], v);
            h2[o] = v > 0.f ? v : 0.f;
        }
        const float* w3 = W3 + g * 16;
        const float* B3 = b3 + g * 4;
        float h3[4];
        #pragma unroll
        for (int o = 0; o < 4; o++) {
            float v = __ldg(&B3[o]);
            #pragma unroll
            for (int h = 0; h < 4; h++) v = fmaf(__ldg(&w3[o * 4 + h]), h2[h], v);
            h3[o] = v > 0.f ? v : 0.f;
        }
        float v = __ldg(&bo[g]);
        #pragma unroll
        for (int h = 0; h < 4; h++) v = fmaf(__ldg(&Wo[g * 4 + h]), h3[h], v);
        float ke = 1.0f / (1.0f + __expf(-v));
        a[2 + g] *= ke;
    }

    // ---- pre-gather per-sample scalars: A4[p] for p = f4_index mod 9 ----
    #pragma unroll
    for (int p = 0; p < 9; p++) {
        float4 v;
        v.x = a[(4 * p)     % 9];
        v.y = a[(4 * p + 1) % 9];
        v.z = a[(4 * p + 2) % 9];
        v.w = a[(4 * p + 3) % 9];
        sa4[tid][p] = v;
    }

    __syncthreads();  // sT4 staged + warp slabs ready (block-wide: covers sT4 too)

    // ---- flat warp-owned write phase (all stores 128B-aligned full lines) ----
    const long long gbase = (long long)blockIdx.x * NS;
    if (gbase + NS <= Ntot) {
        // lane state: f0 = warp*3456 + lane -> r0 = lane, p0 = lane%9
        int r = lane;                       // f4 index within current sample row
        int p = lane % 9;                   // period-9 phase
        const float* pa = (const float*)&sa4[warp * 32][0];   // 36 floats/sample
        float* po = out + (size_t)gbase * ROW + (size_t)4 * (warp * WCHUNK + lane);

        #pragma unroll 4
        for (int it = 0; it < 108; it++) {
            float4 t4 = sT4[r];
            float4 a4 = *(const float4*)(pa + 4 * p);
            float4 o;
            o.x = a4.x * t4.x;
            o.y = a4.y * t4.y;
            o.z = a4.z * t4.z;
            o.w = a4.w * t4.w;
            __stcs((float4*)po, o);
            po += 128;                       // 32 f4 = 128 floats per warp-iter
            p += 5; if (p >= 9) p -= 9;      // 32 mod 9 = 5
            r += 32; if (r >= NF4) { r -= NF4; pa += 36; }
        }
    } else {
        // tail path (bounds-checked, generic)
        const float* sTs = (const float*)sT4;
        for (int i = warp * WCHUNK + lane; i < (warp + 1) * WCHUNK; i += 32) {
            int nl = i / NF4;
            if (gbase + nl >= Ntot) break;
            int k = (i - nl * NF4) * 4;
            const float* pa = (const float*)&sa4[nl][0];
            int p = i % 9;
            float4 a4 = *(const float4*)(pa + 4 * p);
            float4 o;
            o.x = a4.x * sTs[k];
            o.y = a4.y * sTs[k + 1];
            o.z = a4.z * sTs[k + 2];
            o.w = a4.w * sTs[k + 3];
            *(float4*)(out + (size_t)gbase * ROW + (size_t)4 * i) = o;
        }
    }
}

extern "C" void kernel_launch(void* const* d_in, const int* in_sizes, int n_in,
                              void* d_out, int out_size)
{
    const float* t_p   = (const float*)d_in[0];
    const float* c     = (const float*)d_in[1];
    const float* w_lin = (const float*)d_in[2];
    const float* W1    = (const float*)d_in[3];
    const float* b1    = (const float*)d_in[4];
    const float* W2    = (const float*)d_in[5];
    const float* b2    = (const float*)d_in[6];
    const float* W3    = (const float*)d_in[7];
    const float* b3    = (const float*)d_in[8];
    const float* Wo    = (const float*)d_in[9];
    const float* bo    = (const float*)d_in[10];
    float* out = (float*)d_out;

    int Ntot = in_sizes[1] / 9;   // c is [N,9]
    int nblk = (Ntot + NS - 1) / NS;
    fullnet_kernel<<<nblk, NTH>>>(t_p, c, w_lin, W1, b1, W2, b2, W3, b3, Wo, bo,
                                  out, Ntot);
}

// round 9
// speedup vs baseline: 1.1035x; 1.1035x over previous
#include <cuda_runtime.h>

// FullNet_29008209117719: tau[N,48,9] = a[n,j] * T[ch,j]
//   T[ch,j] = exp(w_lin[j,ch]) * (j<2 ? 1 : FILT[j-2,ch])   (constant per launch)
//   a[n,0]=c[n,0]; a[n,1]=c[n,1]; a[n,2+g]=c[n,2+g]*sigmoid(MLP_g(t_p[n]))
// Store-bound: 453 MB output. R5 core loop (best measured: 2x LDS.128 +
// 4 FMUL + 1 streaming STG.128, all stores 128B-aligned full lines) with
// 512-thread CTAs + dynamic smem (73.7KB) -> 3 CTAs/SM x 16 warps =
// 48 warps/SM (vs R5's 40) and grid=512 exactly (no tail), wave tail 1.15.

#define NTH 512
#define NS  512            // samples per block (1 per thread)
#define ROW 432            // 48 channels * 9 species
#define NF4 (ROW / 4)      // 108 float4 per sample row
#define WCHUNK 3456        // f4s per warp = 32 samples * 108
#define NW  497            // total weight floats staged in smem

// dynamic smem layout (float4 units): [0,108) sT4 | [108, 108+NS*9) sa4
#define SMEM_F4   (NF4 + NS * 9)
#define SMEM_BYTES (SMEM_F4 * 16 + NW * 4)

__device__ __constant__ unsigned char d_F16[7][16] = {
    {1,1,1,1,1,1,1,1,1,1,1,1,1,0,1,1},  // h2o
    {0,0,0,1,1,0,1,1,0,0,0,0,1,0,0,0},  // o3
    {0,0,1,1,1,1,1,1,0,0,0,1,1,1,1,0},  // co2
    {1,0,0,0,0,0,0,0,0,0,1,0,0,0,0,0},  // o2
    {0,0,1,0,0,0,0,1,1,0,0,0,1,0,1,0},  // n2o
    {0,0,0,0,0,0,0,0,1,0,0,0,0,0,0,1},  // ch4
    {0,0,0,0,0,0,0,1,0,0,0,0,1,0,0,0},  // co
};

// smem weight layout offsets
#define OFF_W1 0      // 7*6*2 = 84
#define OFF_B1 84     // 7*6   = 42
#define OFF_W2 126    // 7*4*6 = 168
#define OFF_B2 294    // 7*4   = 28
#define OFF_W3 322    // 7*4*4 = 112
#define OFF_B3 434    // 7*4   = 28
#define OFF_WO 462    // 7*4   = 28
#define OFF_BO 490    // 7     = 7   -> 497 total

__global__ __launch_bounds__(NTH, 3) void fullnet_kernel(
    const float* __restrict__ t_p,   // [N,2]
    const float* __restrict__ c,     // [N,9]
    const float* __restrict__ w_lin, // [9,48]
    const float* __restrict__ W1, const float* __restrict__ b1,
    const float* __restrict__ W2, const float* __restrict__ b2,
    const float* __restrict__ W3, const float* __restrict__ b3,
    const float* __restrict__ Wo, const float* __restrict__ bo,
    float* __restrict__ out,         // [N,48,9]
    int Ntot)
{
    extern __shared__ float4 dyn[];
    float4* sT4 = dyn;                       // 108 float4 T table
    float4* sa4 = dyn + NF4;                 // [NS][9] pre-gathered scalars
    float*  sw  = (float*)(dyn + SMEM_F4);   // 497 MLP weight floats

    const int tid  = threadIdx.x;
    const int lane = tid & 31;
    const int warp = tid >> 5;

    // ---- stage weights into smem ----
    for (int i = tid; i < NW; i += NTH) {
        float v;
        if      (i < OFF_B1) v = W1[i - OFF_W1];
        else if (i < OFF_W2) v = b1[i - OFF_B1];
        else if (i < OFF_B2) v = W2[i - OFF_W2];
        else if (i < OFF_W3) v = b2[i - OFF_B2];
        else if (i < OFF_B3) v = W3[i - OFF_W3];
        else if (i < OFF_WO) v = b3[i - OFF_B3];
        else if (i < OFF_BO) v = Wo[i - OFF_WO];
        else                 v = bo[i - OFF_BO];
        sw[i] = v;
    }

    // ---- build constant table T ----
    float* sTf = (float*)sT4;
    for (int k = tid; k < ROW; k += NTH) {
        int ch = k / 9, j = k % 9;
        float m = (j < 2) ? 1.0f : (float)d_F16[j - 2][ch / 3];
        sTf[k] = m * expf(w_lin[j * 48 + ch]);
    }

    // ---- per-sample loads ----
    const int n = blockIdx.x * NS + tid;
    float tt = 0.f, pp = 0.f;
    float a[9];
    if (n < Ntot) {
        tt = t_p[2 * n];
        pp = t_p[2 * n + 1];
        #pragma unroll
        for (int j = 0; j < 9; j++) a[j] = c[9 * n + j];
    } else {
        #pragma unroll
        for (int j = 0; j < 9; j++) a[j] = 0.f;
    }

    __syncthreads();  // sw staged

    // ---- MLPs (one sample per thread); a[2+g] *= sigmoid(ke_g) ----
    #pragma unroll 1
    for (int g = 0; g < 7; g++) {
        const float* w1 = &sw[OFF_W1 + g * 12];
        const float* B1 = &sw[OFF_B1 + g * 6];
        float h1[6];
        #pragma unroll
        for (int h = 0; h < 6; h++) {
            float v = fmaf(w1[2 * h], tt, fmaf(w1[2 * h + 1], pp, B1[h]));
            h1[h] = v > 0.f ? v : 0.f;
        }
        const float* w2 = &sw[OFF_W2 + g * 24];
        const float* B2 = &sw[OFF_B2 + g * 4];
        float h2[4];
        #pragma unroll
        for (int o = 0; o < 4; o++) {
            float v = B2[o];
            #pragma unroll
            for (int h = 0; h < 6; h++) v = fmaf(w2[o * 6 + h], h1[h], v);
            h2[o] = v > 0.f ? v : 0.f;
        }
        const float* w3 = &sw[OFF_W3 + g * 16];
        const float* B3 = &sw[OFF_B3 + g * 4];
        float h3[4];
        #pragma unroll
        for (int o = 0; o < 4; o++) {
            float v = B3[o];
            #pragma unroll
            for (int h = 0; h < 4; h++) v = fmaf(w3[o * 4 + h], h2[h], v);
            h3[o] = v > 0.f ? v : 0.f;
        }
        float v = sw[OFF_BO + g];
        #pragma unroll
        for (int h = 0; h < 4; h++) v = fmaf(sw[OFF_WO + g * 4 + h], h3[h], v);
        float ke = 1.0f / (1.0f + __expf(-v));
        a[2 + g] *= ke;
    }

    // ---- pre-gather per-sample scalars: A4[p] for p = f4_index mod 9 ----
    #pragma unroll
    for (int p = 0; p < 9; p++) {
        float4 v;
        v.x = a[(4 * p)     % 9];
        v.y = a[(4 * p + 1) % 9];
        v.z = a[(4 * p + 2) % 9];
        v.w = a[(4 * p + 3) % 9];
        sa4[tid * 9 + p] = v;
    }

    __syncwarp();  // warp w's flat chunk covers exactly samples [32w, 32w+32)

    // ---- flat warp-owned write phase (all stores 128B-aligned full lines) ----
    const long long gbase = (long long)blockIdx.x * NS;
    if (gbase + NS <= Ntot) {
        // lane state: f0 = warp*3456 + lane -> r0 = lane, p0 = lane%9
        int r = lane;                       // f4 index within current sample row
        int p = lane % 9;                   // period-9 phase
        const float* pa = (const float*)(sa4 + (size_t)warp * 32 * 9);  // 36 f/sample
        float* po = out + (size_t)gbase * ROW + (size_t)4 * (warp * WCHUNK + lane);

        #pragma unroll 4
        for (int it = 0; it < 108; it++) {
            float4 t4 = sT4[r];
            float4 a4 = *(const float4*)(pa + 4 * p);
            float4 o;
            o.x = a4.x * t4.x;
            o.y = a4.y * t4.y;
            o.z = a4.z * t4.z;
            o.w = a4.w * t4.w;
            __stcs((float4*)po, o);
            po += 128;                       // 32 f4 = 128 floats per warp-iter
            p += 5; if (p >= 9) p -= 9;      // 32 mod 9 = 5
            r += 32; if (r >= NF4) { r -= NF4; pa += 36; }
        }
    } else {
        // tail path (bounds-checked, generic)
        const float* sTs = (const float*)sT4;
        for (int i = warp * WCHUNK + lane; i < (warp + 1) * WCHUNK; i += 32) {
            int nl = i / NF4;
            if (gbase + nl >= Ntot) break;
            int k = (i - nl * NF4) * 4;
            const float* pa = (const float*)(sa4 + (size_t)nl * 9);
            int p = i % 9;
            float4 a4 = *(const float4*)(pa + 4 * p);
            float4 o;
            o.x = a4.x * sTs[k];
            o.y = a4.y * sTs[k + 1];
            o.z = a4.z * sTs[k + 2];
            o.w = a4.w * sTs[k + 3];
            *(float4*)(out + (size_t)gbase * ROW + (size_t)4 * i) = o;
        }
    }
}

extern "C" void kernel_launch(void* const* d_in, const int* in_sizes, int n_in,
                              void* d_out, int out_size)
{
    const float* t_p   = (const float*)d_in[0];
    const float* c     = (const float*)d_in[1];
    const float* w_lin = (const float*)d_in[2];
    const float* W1    = (const float*)d_in[3];
    const float* b1    = (const float*)d_in[4];
    const float* W2    = (const float*)d_in[5];
    const float* b2    = (const float*)d_in[6];
    const float* W3    = (const float*)d_in[7];
    const float* b3    = (const float*)d_in[8];
    const float* Wo    = (const float*)d_in[9];
    const float* bo    = (const float*)d_in[10];
    float* out = (float*)d_out;

    int Ntot = in_sizes[1] / 9;   // c is [N,9]
    int nblk = (Ntot + NS - 1) / NS;

    // >48KB dynamic smem opt-in (host-side attribute set; not a stream op,
    // no allocation — graph-capture safe and idempotent)
    cudaFuncSetAttribute(fullnet_kernel,
                         cudaFuncAttributeMaxDynamicSharedMemorySize,
                         SMEM_BYTES);

    fullnet_kernel<<<nblk, NTH, SMEM_BYTES>>>(t_p, c, w_lin, W1, b1, W2, b2,
                                              W3, b3, Wo, bo, out, Ntot);
}

// round 11
// speedup vs baseline: 1.1748x; 1.0646x over previous
#include <cuda_runtime.h>

// FullNet_29008209117719: tau[N,48,9] = a[n,j] * T[ch,j]
//   T[ch,j] = exp(w_lin[j,ch]) * (j<2 ? 1 : FILT[j-2,ch])   (constant per launch)
//   a[n,0]=c[n,0]; a[n,1]=c[n,1]; a[n,2+g]=c[n,2+g]*sigmoid(MLP_g(t_p[n]))
// Store-bound: 453 MB output. L1-crossbar-optimized write phase:
//   slot-ordered traversal keeps T in REGISTERS (0 crossbar phases) and makes
//   the a4 load a same-sample broadcast (~2 phases), vs R5's ~8 read phases.
//   Inner loop: 1 LDS.128 + 4 FMUL + 1 streaming STG.128, unroll 8.
// R10 bug fixed: phase for f4-slot m is p = m % 9 (sa4[n][p] holds the
// scalars for f4-indices ≡ p mod 9), not (4m) % 9.

#define NTH 256
#define NS  256            // samples per block (1 per thread)
#define ROW 432            // 48 channels * 9 species
#define NF4 (ROW / 4)      // 108 float4 per sample row
#define WCHUNK 3456        // f4s per warp slab = 32 samples * 108
#define NW  497            // total weight floats staged in smem

__device__ __constant__ unsigned char d_F16[7][16] = {
    {1,1,1,1,1,1,1,1,1,1,1,1,1,0,1,1},  // h2o
    {0,0,0,1,1,0,1,1,0,0,0,0,1,0,0,0},  // o3
    {0,0,1,1,1,1,1,1,0,0,0,1,1,1,1,0},  // co2
    {1,0,0,0,0,0,0,0,0,0,1,0,0,0,0,0},  // o2
    {0,0,1,0,0,0,0,1,1,0,0,0,1,0,1,0},  // n2o
    {0,0,0,0,0,0,0,0,1,0,0,0,0,0,0,1},  // ch4
    {0,0,0,0,0,0,0,1,0,0,0,0,1,0,0,0},  // co
};

// smem weight layout offsets
#define OFF_W1 0      // 7*6*2 = 84
#define OFF_B1 84     // 7*6   = 42
#define OFF_W2 126    // 7*4*6 = 168
#define OFF_B2 294    // 7*4   = 28
#define OFF_W3 322    // 7*4*4 = 112
#define OFF_B3 434    // 7*4   = 28
#define OFF_WO 462    // 7*4   = 28
#define OFF_BO 490    // 7     = 7   -> 497 total

__global__ __launch_bounds__(NTH) void fullnet_kernel(
    const float* __restrict__ t_p,   // [N,2]
    const float* __restrict__ c,     // [N,9]
    const float* __restrict__ w_lin, // [9,48]
    const float* __restrict__ W1, const float* __restrict__ b1,
    const float* __restrict__ W2, const float* __restrict__ b2,
    const float* __restrict__ W3, const float* __restrict__ b3,
    const float* __restrict__ Wo, const float* __restrict__ bo,
    float* __restrict__ out,         // [N,48,9]
    int Ntot)
{
    __shared__ float4 sT4[NF4];       // T table as 108 float4
    __shared__ float4 sa4[NS][9];     // per-sample pre-gathered scalars
    __shared__ float  sw[NW];         // all MLP weights

    const int tid  = threadIdx.x;
    const int lane = tid & 31;
    const int warp = tid >> 5;

    // ---- stage weights into smem ----
    for (int i = tid; i < NW; i += NTH) {
        float v;
        if      (i < OFF_B1) v = W1[i - OFF_W1];
        else if (i < OFF_W2) v = b1[i - OFF_B1];
        else if (i < OFF_B2) v = W2[i - OFF_W2];
        else if (i < OFF_W3) v = b2[i - OFF_B2];
        else if (i < OFF_B3) v = W3[i - OFF_W3];
        else if (i < OFF_WO) v = b3[i - OFF_B3];
        else if (i < OFF_BO) v = Wo[i - OFF_WO];
        else                 v = bo[i - OFF_BO];
        sw[i] = v;
    }

    // ---- build constant table T ----
    float* sTf = (float*)sT4;
    for (int k = tid; k < ROW; k += NTH) {
        int ch = k / 9, j = k % 9;
        float m = (j < 2) ? 1.0f : (float)d_F16[j - 2][ch / 3];
        sTf[k] = m * expf(w_lin[j * 48 + ch]);
    }

    // ---- per-sample loads ----
    const int n = blockIdx.x * NS + tid;
    float tt = 0.f, pp = 0.f;
    float a[9];
    if (n < Ntot) {
        tt = t_p[2 * n];
        pp = t_p[2 * n + 1];
        #pragma unroll
        for (int j = 0; j < 9; j++) a[j] = c[9 * n + j];
    } else {
        #pragma unroll
        for (int j = 0; j < 9; j++) a[j] = 0.f;
    }

    __syncthreads();  // sw staged

    // ---- MLPs (one sample per thread); a[2+g] *= sigmoid(ke_g) ----
    #pragma unroll 1
    for (int g = 0; g < 7; g++) {
        const float* w1 = &sw[OFF_W1 + g * 12];
        const float* B1 = &sw[OFF_B1 + g * 6];
        float h1[6];
        #pragma unroll
        for (int h = 0; h < 6; h++) {
            float v = fmaf(w1[2 * h], tt, fmaf(w1[2 * h + 1], pp, B1[h]));
            h1[h] = v > 0.f ? v : 0.f;
        }
        const float* w2 = &sw[OFF_W2 + g * 24];
        const float* B2 = &sw[OFF_B2 + g * 4];
        float h2[4];
        #pragma unroll
        for (int o = 0; o < 4; o++) {
            float v = B2[o];
            #pragma unroll
            for (int h = 0; h < 6; h++) v = fmaf(w2[o * 6 + h], h1[h], v);
            h2[o] = v > 0.f ? v : 0.f;
        }
        const float* w3 = &sw[OFF_W3 + g * 16];
        const float* B3 = &sw[OFF_B3 + g * 4];
        float h3[4];
        #pragma unroll
        for (int o = 0; o < 4; o++) {
            float v = B3[o];
            #pragma unroll
            for (int h = 0; h < 4; h++) v = fmaf(w3[o * 4 + h], h2[h], v);
            h3[o] = v > 0.f ? v : 0.f;
        }
        float v = sw[OFF_BO + g];
        #pragma unroll
        for (int h = 0; h < 4; h++) v = fmaf(sw[OFF_WO + g * 4 + h], h3[h], v);
        float ke = 1.0f / (1.0f + __expf(-v));
        a[2 + g] *= ke;
    }

    // ---- pre-gather per-sample scalars: sa4[n][p] serves f4-indices ≡ p (mod 9) ----
    #pragma unroll
    for (int p = 0; p < 9; p++) {
        float4 v;
        v.x = a[(4 * p)     % 9];
        v.y = a[(4 * p + 1) % 9];
        v.z = a[(4 * p + 2) % 9];
        v.w = a[(4 * p + 3) % 9];
        sa4[tid][p] = v;
    }

    __syncwarp();  // warp w's slab (samples [32w,32w+32)) is ready

    // ---- slot-ordered warp-owned write phase ----
    // Lane L owns f4-slots m = L, L+32, L+64, (L+96 if L<12). Per slot:
    // t4 = sT4[m] held in REGISTERS for 32 samples; phase p = m % 9 constant.
    // Inner loop over the warp's 32 samples: all lanes read the SAME sample's
    // sa4 row (9 f4s in 144B -> ~2 crossbar phases) + 4 FMUL + STG.128 (.cs).
    const long long gbase = (long long)blockIdx.x * NS;
    if (gbase + NS <= Ntot) {
        const float* paw = (const float*)&sa4[warp * 32][0];  // 36 floats/sample
        float* outw = out + (size_t)(gbase + warp * 32) * ROW;

        #pragma unroll
        for (int slot = 0; slot < 4; slot++) {
            const int m = lane + slot * 32;
            if (slot == 3 && lane >= 12) break;   // only 12 lanes in last slot
            const float4 t4 = sT4[m];
            const int p = m % 9;                  // FIXED: f4-index mod 9
            const float* pa = paw + 4 * p;
            float* po = outw + 4 * m;
            #pragma unroll 8
            for (int s = 0; s < 32; s++) {
                float4 a4 = *(const float4*)pa;
                float4 o;
                o.x = a4.x * t4.x;
                o.y = a4.y * t4.y;
                o.z = a4.z * t4.z;
                o.w = a4.w * t4.w;
                __stcs((float4*)po, o);
                pa += 36;      // next sample's sa4 row
                po += ROW;     // next sample's output row
            }
        }
    } else {
        // tail path (bounds-checked, generic)
        const float* sTs = (const float*)sT4;
        for (int i = warp * WCHUNK + lane; i < (warp + 1) * WCHUNK; i += 32) {
            int nl = i / NF4;
            if (gbase + nl >= Ntot) break;
            int k = (i - nl * NF4) * 4;
            const float* pa = (const float*)&sa4[nl][0];
            int p = i % 9;
            float4 a4 = *(const float4*)(pa + 4 * p);
            float4 o;
            o.x = a4.x * sTs[k];
            o.y = a4.y * sTs[k + 1];
            o.z = a4.z * sTs[k + 2];
            o.w = a4.w * sTs[k + 3];
            *(float4*)(out + (size_t)gbase * ROW + (size_t)4 * i) = o;
        }
    }
}

extern "C" void kernel_launch(void* const* d_in, const int* in_sizes, int n_in,
                              void* d_out, int out_size)
{
    const float* t_p   = (const float*)d_in[0];
    const float* c     = (const float*)d_in[1];
    const float* w_lin = (const float*)d_in[2];
    const float* W1    = (const float*)d_in[3];
    const float* b1    = (const float*)d_in[4];
    const float* W2    = (const float*)d_in[5];
    const float* b2    = (const float*)d_in[6];
    const float* W3    = (const float*)d_in[7];
    const float* b3    = (const float*)d_in[8];
    const float* Wo    = (const float*)d_in[9];
    const float* bo    = (const float*)d_in[10];
    float* out = (float*)d_out;

    int Ntot = in_sizes[1] / 9;   // c is [N,9]
    int nblk = (Ntot + NS - 1) / NS;
    fullnet_kernel<<<nblk, NTH>>>(t_p, c, w_lin, W1, b1, W2, b2, W3, b3, Wo, bo,
                                  out, Ntot);
}